// round 1
// baseline (speedup 1.0000x reference)
#include <cuda_runtime.h>
#include <cstddef>

// Problem constants
#define B_ 4
#define NT 16384
#define DM 128
#define SPLITS 64
#define CHUNK (NT / SPLITS)   // 256 rows per split

// Scratch (__device__ globals — allocation-free)
// g_part doubles as: G partials [64][4][128][128], then Wfin partials [8][4][128][128]
static __device__ float g_part[SPLITS * B_ * DM * DM];  // 16.8 MB
static __device__ float g_G   [B_ * DM * DM];
static __device__ float g_A   [B_ * 512 * DM];
static __device__ float g_D   [32 * 64 * 64];
static __device__ float g_E   [B_ * 128 * 512];
static __device__ float g_Wfin[B_ * DM * DM];

// ---- packed f32x2 helpers (Blackwell) ----
__device__ __forceinline__ unsigned long long pack2(float x, float y) {
    unsigned long long r;
    asm("mov.b64 %0, {%1,%2};" : "=l"(r) : "f"(x), "f"(y));
    return r;
}
__device__ __forceinline__ void fma2(unsigned long long& c, unsigned long long a,
                                     unsigned long long b) {
    asm("fma.rn.f32x2 %0, %1, %2, %3;" : "=l"(c) : "l"(a), "l"(b), "l"(c));
}
__device__ __forceinline__ float2 unpack2(unsigned long long v) {
    float2 f;
    asm("mov.b64 {%0,%1}, %2;" : "=f"(f.x), "=f"(f.y) : "l"(v));
    return f;
}

// ---------------------------------------------------------------------------
// 64x64 output tile GEMM core, 256 threads, 4x4 register tile, k-chunk 16.
// TA: A accessed as A[k*lda + m] (i.e. A is K-major / "transposed" view)
// !TA: A[m*lda + k].  TB: B[n*ldb + k].  !TB: B[k*ldb + n].
// All dims assumed multiples of the tile (true for this problem).
// ---------------------------------------------------------------------------
template <bool TA, bool TB>
__device__ __forceinline__ void gemm_tile(const float* __restrict__ A,
                                          const float* __restrict__ B,
                                          float* __restrict__ C, int K, int lda,
                                          int ldb, int ldc,
                                          const float* __restrict__ bias) {
    __shared__ float sA[16][68];  // sA[k][m], pitch 68 floats (16B-aligned rows)
    __shared__ float sB[16][68];  // sB[k][n]
    const int t = threadIdx.x;
    const int tx = t & 15, ty = t >> 4;

    unsigned long long acc[4][2];
#pragma unroll
    for (int i = 0; i < 4; i++) { acc[i][0] = 0ULL; acc[i][1] = 0ULL; }

    for (int k0 = 0; k0 < K; k0 += 16) {
        if (TA) {
            const int kk = t >> 4, m4 = (t & 15) << 2;
            float4 v = *(const float4*)(A + (size_t)(k0 + kk) * lda + m4);
            *(float4*)&sA[kk][m4] = v;
        } else {
            const int m = t >> 2, k4 = (t & 3) << 2;
            float4 v = *(const float4*)(A + (size_t)m * lda + k0 + k4);
            sA[k4 + 0][m] = v.x; sA[k4 + 1][m] = v.y;
            sA[k4 + 2][m] = v.z; sA[k4 + 3][m] = v.w;
        }
        if (!TB) {
            const int kk = t >> 4, n4 = (t & 15) << 2;
            float4 v = *(const float4*)(B + (size_t)(k0 + kk) * ldb + n4);
            *(float4*)&sB[kk][n4] = v;
        } else {
            const int n = t >> 2, k4 = (t & 3) << 2;
            float4 v = *(const float4*)(B + (size_t)n * ldb + k0 + k4);
            sB[k4 + 0][n] = v.x; sB[k4 + 1][n] = v.y;
            sB[k4 + 2][n] = v.z; sB[k4 + 3][n] = v.w;
        }
        __syncthreads();
#pragma unroll
        for (int kk = 0; kk < 16; kk++) {
            const float4 a = *(const float4*)&sA[kk][ty << 2];
            const ulonglong2 bb = *(const ulonglong2*)&sB[kk][tx << 2];
            unsigned long long a0 = pack2(a.x, a.x), a1 = pack2(a.y, a.y);
            unsigned long long a2 = pack2(a.z, a.z), a3 = pack2(a.w, a.w);
            fma2(acc[0][0], a0, bb.x); fma2(acc[0][1], a0, bb.y);
            fma2(acc[1][0], a1, bb.x); fma2(acc[1][1], a1, bb.y);
            fma2(acc[2][0], a2, bb.x); fma2(acc[2][1], a2, bb.y);
            fma2(acc[3][0], a3, bb.x); fma2(acc[3][1], a3, bb.y);
        }
        __syncthreads();
    }

    float4 bv = make_float4(0.f, 0.f, 0.f, 0.f);
    if (bias) bv = *(const float4*)(bias + (tx << 2));
#pragma unroll
    for (int i = 0; i < 4; i++) {
        float2 lo = unpack2(acc[i][0]);
        float2 hi = unpack2(acc[i][1]);
        float4 r = make_float4(lo.x + bv.x, lo.y + bv.y, hi.x + bv.z, hi.y + bv.w);
        *(float4*)(C + (size_t)((ty << 2) + i) * ldc + (tx << 2)) = r;
    }
}

// ---- Stage 1: G partials.  G[b] = keys[b]^T @ values[b], split-K over 64 chunks
__global__ void __launch_bounds__(256) k_gemm_g(const float* __restrict__ keys,
                                                const float* __restrict__ values) {
    const int b = blockIdx.z & 3, sp = blockIdx.z >> 2;
    const int n0 = blockIdx.x << 6, m0 = blockIdx.y << 6;
    const float* A = keys   + (size_t)b * NT * DM + (size_t)sp * CHUNK * DM + m0;
    const float* Bp = values + (size_t)b * NT * DM + (size_t)sp * CHUNK * DM + n0;
    float* C = g_part + (size_t)sp * (B_ * DM * DM) + (size_t)b * (DM * DM) +
               (size_t)m0 * DM + n0;
    gemm_tile<true, false>(A, Bp, C, CHUNK, DM, DM, DM, nullptr);
}

__global__ void __launch_bounds__(256) k_reduce_G() {
    const int i = blockIdx.x * 256 + threadIdx.x;  // 65536 total
    float s = 0.f;
#pragma unroll 8
    for (int p = 0; p < SPLITS; p++) s += g_part[(size_t)p * (B_ * DM * DM) + i];
    g_G[i] = s;
}

// ---- Stage 2: A_all[b] = Wk @ G[b]   [512,128] = [512,128]x[128,128]
__global__ void __launch_bounds__(256) k_gemm_a(const float* __restrict__ Wk) {
    const int b = blockIdx.z;
    const int m0 = blockIdx.y << 6, n0 = blockIdx.x << 6;
    const float* A = Wk + (size_t)m0 * DM;
    const float* Bp = g_G + (size_t)b * DM * DM + n0;
    float* C = g_A + (size_t)b * 512 * DM + (size_t)m0 * DM + n0;
    gemm_tile<false, false>(A, Bp, C, DM, DM, DM, DM, nullptr);
}

// ---- Stage 3: D[b,h] = A_h @ Wk_h^T   [64,64]
__global__ void __launch_bounds__(256) k_gemm_d(const float* __restrict__ Wk) {
    const int b = blockIdx.z >> 3, h = blockIdx.z & 7;
    const float* A = g_A + (size_t)b * 512 * DM + (size_t)h * 64 * DM;
    const float* Bp = Wk + (size_t)h * 64 * DM;
    float* C = g_D + (size_t)blockIdx.z * 64 * 64;
    gemm_tile<false, true>(A, Bp, C, DM, DM, DM, 64, nullptr);
}

// ---- Stage 4: Ecat[b][:, h*64:+64] = Wq_h^T @ D[b,h]   [128,64]
__global__ void __launch_bounds__(256) k_gemm_e(const float* __restrict__ Wq) {
    const int b = blockIdx.z >> 3, h = blockIdx.z & 7;
    const int m0 = blockIdx.y << 6;
    const float* A = Wq + (size_t)h * 64 * DM + m0;  // TA view: A[k][m]
    const float* Bp = g_D + (size_t)blockIdx.z * 64 * 64;
    float* C = g_E + (size_t)b * 128 * 512 + (size_t)m0 * 512 + h * 64;
    gemm_tile<true, false>(A, Bp, C, 64, DM, 64, 512, nullptr);
}

// ---- Stage 5: Wfin partials.  Wfin[b] = Ecat[b] @ Wo^T, split-K over 8 chunks
__global__ void __launch_bounds__(256) k_gemm_f(const float* __restrict__ Wo) {
    const int b = blockIdx.z & 3, sp = blockIdx.z >> 2;
    const int m0 = blockIdx.y << 6, n0 = blockIdx.x << 6;
    const float* A = g_E + (size_t)b * 128 * 512 + (size_t)m0 * 512 + sp * 64;
    const float* Bp = Wo + (size_t)n0 * 512 + sp * 64;
    float* C = g_part + (size_t)sp * (B_ * DM * DM) + (size_t)b * (DM * DM) +
               (size_t)m0 * DM + n0;
    gemm_tile<false, true>(A, Bp, C, 64, 512, 512, DM, nullptr);
}

__global__ void __launch_bounds__(256) k_reduce_F() {
    const int i = blockIdx.x * 256 + threadIdx.x;  // 65536 total
    float s = 0.f;
#pragma unroll
    for (int p = 0; p < 8; p++) s += g_part[(size_t)p * (B_ * DM * DM) + i];
    g_Wfin[i] = s * (1.0f / (float)NT);
}

// ---- Stage 6: out[b] = queries[b] @ Wfin[b] + bo
__global__ void __launch_bounds__(256) k_gemm_out(const float* __restrict__ q,
                                                  const float* __restrict__ bo,
                                                  float* __restrict__ out) {
    const int b = blockIdx.z;
    const int m0 = blockIdx.y << 6, n0 = blockIdx.x << 6;
    const float* A = q + (size_t)b * NT * DM + (size_t)m0 * DM;
    const float* Bp = g_Wfin + (size_t)b * DM * DM + n0;
    float* C = out + (size_t)b * NT * DM + (size_t)m0 * DM + n0;
    gemm_tile<false, false>(A, Bp, C, DM, DM, DM, DM, bo + n0);
}

extern "C" void kernel_launch(void* const* d_in, const int* in_sizes, int n_in,
                              void* d_out, int out_size) {
    // metadata order: queries, keys, values, Wq, Wk, Wo, bo
    const float* queries = (const float*)d_in[0];
    const float* keys    = (const float*)d_in[1];
    const float* values  = (const float*)d_in[2];
    const float* Wq      = (const float*)d_in[3];
    const float* Wk      = (const float*)d_in[4];
    const float* Wo      = (const float*)d_in[5];
    const float* bo      = (const float*)d_in[6];
    float* out = (float*)d_out;

    k_gemm_g  <<<dim3(2, 2, B_ * SPLITS), 256>>>(keys, values);
    k_reduce_G<<<256, 256>>>();
    k_gemm_a  <<<dim3(2, 8, B_), 256>>>(Wk);
    k_gemm_d  <<<dim3(1, 1, 32), 256>>>(Wk);
    k_gemm_e  <<<dim3(1, 2, 32), 256>>>(Wq);
    k_gemm_f  <<<dim3(2, 2, 32), 256>>>(Wo);
    k_reduce_F<<<256, 256>>>();
    k_gemm_out<<<dim3(2, 256, B_), 256>>>(queries, bo, out);
}